// round 4
// baseline (speedup 1.0000x reference)
#include <cuda_runtime.h>
#include <cuda_bf16.h>

// Local Moran's I:
//   xbar = mean(X)
//   xn_ij = X[ids[i][j]] - xbar
//   S_i   = sum_j w_ij * xn_ij^2
//   lag_i = sum_j w_ij * xn_ij
//   out_i = (X[i]-xbar) * lag_i * (K-1) / S_i
//
// N = 1,000,000, K = 32.

#define KNBR 32
#define NUM_PARTIAL_BLOCKS 1024

__device__ float g_partials[NUM_PARTIAL_BLOCKS];
__device__ float g_mean;

// ---------------- Stage 1: per-block partial sums (deterministic order) ----
__global__ void moran_sum_kernel(const float* __restrict__ X, int n) {
    __shared__ float sh[256];
    float s = 0.0f;
    for (int i = blockIdx.x * blockDim.x + threadIdx.x; i < n;
         i += gridDim.x * blockDim.x) {
        s += X[i];
    }
    sh[threadIdx.x] = s;
    __syncthreads();
#pragma unroll
    for (int off = 128; off > 0; off >>= 1) {
        if (threadIdx.x < off) sh[threadIdx.x] += sh[threadIdx.x + off];
        __syncthreads();
    }
    if (threadIdx.x == 0) g_partials[blockIdx.x] = sh[0];
}

// ---------------- Stage 2: reduce partials -> mean --------------------------
__global__ void moran_finalize_mean_kernel(int n) {
    __shared__ float sh[NUM_PARTIAL_BLOCKS];
    sh[threadIdx.x] = g_partials[threadIdx.x];
    __syncthreads();
#pragma unroll
    for (int off = NUM_PARTIAL_BLOCKS / 2; off > 0; off >>= 1) {
        if (threadIdx.x < off) sh[threadIdx.x] += sh[threadIdx.x + off];
        __syncthreads();
    }
    if (threadIdx.x == 0) g_mean = sh[0] / (float)n;
}

// ---------------- Stage 3: main Local Moran kernel --------------------------
__global__ __launch_bounds__(256) void moran_main_kernel(
    const float* __restrict__ X,
    const float4* __restrict__ W,    // [N, 8] float4 view of [N, 32]
    const int4* __restrict__ IDS,    // [N, 8] int4 view of [N, 32]
    float* __restrict__ out, int n) {
    int i = blockIdx.x * blockDim.x + threadIdx.x;
    if (i >= n) return;

    const float mean = g_mean;
    const float4* wrow = W + (size_t)i * (KNBR / 4);
    const int4* idrow = IDS + (size_t)i * (KNBR / 4);

    float lag = 0.0f;
    float S = 0.0f;

#pragma unroll
    for (int j = 0; j < KNBR / 4; j++) {
        float4 w = __ldg(wrow + j);
        int4 id = __ldg(idrow + j);

        float x0 = __ldg(X + id.x) - mean;
        float x1 = __ldg(X + id.y) - mean;
        float x2 = __ldg(X + id.z) - mean;
        float x3 = __ldg(X + id.w) - mean;

        float t0 = w.x * x0;
        float t1 = w.y * x1;
        float t2 = w.z * x2;
        float t3 = w.w * x3;

        lag += t0 + t1 + t2 + t3;
        S = fmaf(t0, x0, S);
        S = fmaf(t1, x1, S);
        S = fmaf(t2, x2, S);
        S = fmaf(t3, x3, S);
    }

    float xa = X[i] - mean;
    out[i] = xa * lag * (float)(KNBR - 1) / S;
}

extern "C" void kernel_launch(void* const* d_in, const int* in_sizes, int n_in,
                              void* d_out, int out_size) {
    const float* X = (const float*)d_in[0];
    const float* W = (const float*)d_in[1];
    const int* IDS = (const int*)d_in[2];
    float* out = (float*)d_out;
    int n = in_sizes[0];

    // Stage 1+2: deterministic mean
    moran_sum_kernel<<<NUM_PARTIAL_BLOCKS, 256>>>(X, n);
    moran_finalize_mean_kernel<<<1, NUM_PARTIAL_BLOCKS>>>(n);

    // Stage 3: main kernel
    int threads = 256;
    int blocks = (n + threads - 1) / threads;
    moran_main_kernel<<<blocks, threads>>>(
        X, (const float4*)W, (const int4*)IDS, out, n);
}